// round 1
// baseline (speedup 1.0000x reference)
#include <cuda_runtime.h>
#include <math.h>

#define Bb 8
#define Nn 4096
#define Dd 256
#define Ee 65536
#define NODES (Bb * Nn)        // 32768
#define EDGES (Bb * Ee)        // 524288
#define G3D   (3 * Dd)         // 768

// ---------------- scratch (static device globals; no allocation) -------------
__device__ float d_m[NODES * Dd];          // h @ W
__device__ float d_agg[NODES * Dd];        // segment-summed messages
__device__ float d_gi[NODES * G3D];        // agg @ W_ih^T + b_ih
__device__ float d_gh[NODES * G3D];        // h   @ W_hh^T + b_hh
__device__ float d_WihT[Dd * G3D];         // [256 x 768]
__device__ float d_WhhT[Dd * G3D];         // [256 x 768]
__device__ int   d_counts[NODES];
__device__ int   d_cursor[NODES];
__device__ int   d_rowptr[NODES + 1];
__device__ int   d_esrc[EDGES];
__device__ float d_eww[EDGES];

// ---------------- CSR construction -------------------------------------------
__global__ void k_zero() {
    int i = blockIdx.x * blockDim.x + threadIdx.x;
    if (i < NODES) { d_counts[i] = 0; d_cursor[i] = 0; }
}

__global__ void k_count(const int* __restrict__ ei, const int* __restrict__ mask) {
    int idx = blockIdx.x * blockDim.x + threadIdx.x;
    if (idx >= EDGES) return;
    int b = idx >> 16;              // E = 65536
    int e = idx & (Ee - 1);
    int u = ei[((b << 1) + 0) * Ee + e];
    int v = ei[((b << 1) + 1) * Ee + e];
    if (mask[(b << 12) + u] > 0 && mask[(b << 12) + v] > 0)
        atomicAdd(&d_counts[(b << 12) + v], 1);
}

// single block, 1024 threads; exclusive scan of 32768 counts -> rowptr
__global__ void k_scan() {
    __shared__ int sums[1024];
    int t = threadIdx.x;
    int base = t * 32;
    int s = 0;
    #pragma unroll
    for (int i = 0; i < 32; i++) s += d_counts[base + i];
    sums[t] = s;
    __syncthreads();
    for (int off = 1; off < 1024; off <<= 1) {
        int v = (t >= off) ? sums[t - off] : 0;
        __syncthreads();
        sums[t] += v;
        __syncthreads();
    }
    int run = (t == 0) ? 0 : sums[t - 1];
    #pragma unroll
    for (int i = 0; i < 32; i++) {
        d_rowptr[base + i] = run;
        run += d_counts[base + i];
    }
    if (t == 1023) d_rowptr[NODES] = sums[1023];
}

__global__ void k_fill(const int* __restrict__ ei, const int* __restrict__ mask,
                       const float* __restrict__ ew) {
    int idx = blockIdx.x * blockDim.x + threadIdx.x;
    if (idx >= EDGES) return;
    int b = idx >> 16;
    int e = idx & (Ee - 1);
    int u = ei[((b << 1) + 0) * Ee + e];
    int v = ei[((b << 1) + 1) * Ee + e];
    if (mask[(b << 12) + u] > 0 && mask[(b << 12) + v] > 0) {
        int node = (b << 12) + v;
        int pos = d_rowptr[node] + atomicAdd(&d_cursor[node], 1);
        d_esrc[pos] = u;
        d_eww[pos]  = ew[idx];          // idx == b*E + e
    }
}

// ---------------- weight transposes: [768,256] -> [256,768] ------------------
__global__ void k_transpose(const float* __restrict__ wih, const float* __restrict__ whh) {
    int idx = blockIdx.x * blockDim.x + threadIdx.x;   // 196608
    if (idx >= G3D * Dd) return;
    int j = idx >> 8;       // 0..767 (row of W_ih)
    int k = idx & 255;      // 0..255
    d_WihT[k * G3D + j] = wih[idx];
    d_WhhT[k * G3D + j] = whh[idx];
}

// ---------------- SGEMM: C[M,N] = A[M,K] @ B[K,N] (+ bias[N]) ----------------
// 128x128 block tile, BK=8, 256 threads, 8x8 microtile. All dims multiples.
__global__ __launch_bounds__(256, 2) void sgemm_128x128(
    const float* __restrict__ A, const float* __restrict__ Bm,
    float* __restrict__ C, const float* __restrict__ bias,
    int M, int N, int K)
{
    __shared__ float As[8][128];
    __shared__ float Bs[8][128];

    const int t  = threadIdx.x;
    const int m0 = blockIdx.y * 128;
    const int n0 = blockIdx.x * 128;

    const int aRow = t >> 1;
    const int aCol = (t & 1) << 2;
    const int bRow = t >> 5;
    const int bCol = (t & 31) << 2;

    const int tx = t & 15;
    const int ty = t >> 4;

    float acc[8][8];
    #pragma unroll
    for (int i = 0; i < 8; i++)
        #pragma unroll
        for (int j = 0; j < 8; j++) acc[i][j] = 0.0f;

    const float* Aptr = A + (size_t)(m0 + aRow) * K + aCol;
    const float* Bptr = Bm + (size_t)bRow * N + n0 + bCol;

    for (int k0 = 0; k0 < K; k0 += 8) {
        float4 a = *(const float4*)(Aptr + k0);
        float4 b = *(const float4*)(Bptr + (size_t)k0 * N);
        As[aCol + 0][aRow] = a.x;
        As[aCol + 1][aRow] = a.y;
        As[aCol + 2][aRow] = a.z;
        As[aCol + 3][aRow] = a.w;
        *(float4*)&Bs[bRow][bCol] = b;
        __syncthreads();

        #pragma unroll
        for (int kk = 0; kk < 8; ++kk) {
            float4 a0 = *(const float4*)&As[kk][ty * 8];
            float4 a1 = *(const float4*)&As[kk][ty * 8 + 4];
            float4 b0 = *(const float4*)&Bs[kk][tx * 8];
            float4 b1 = *(const float4*)&Bs[kk][tx * 8 + 4];
            float ar[8] = {a0.x, a0.y, a0.z, a0.w, a1.x, a1.y, a1.z, a1.w};
            float br[8] = {b0.x, b0.y, b0.z, b0.w, b1.x, b1.y, b1.z, b1.w};
            #pragma unroll
            for (int i = 0; i < 8; i++)
                #pragma unroll
                for (int j = 0; j < 8; j++)
                    acc[i][j] = fmaf(ar[i], br[j], acc[i][j]);
        }
        __syncthreads();
    }

    // epilogue
    #pragma unroll
    for (int i = 0; i < 8; i++) {
        int row = m0 + ty * 8 + i;
        float* cptr = C + (size_t)row * N + n0 + tx * 8;
        float4 v0 = make_float4(acc[i][0], acc[i][1], acc[i][2], acc[i][3]);
        float4 v1 = make_float4(acc[i][4], acc[i][5], acc[i][6], acc[i][7]);
        if (bias) {
            const float* bp = bias + n0 + tx * 8;
            v0.x += bp[0]; v0.y += bp[1]; v0.z += bp[2]; v0.w += bp[3];
            v1.x += bp[4]; v1.y += bp[5]; v1.z += bp[6]; v1.w += bp[7];
        }
        *(float4*)(cptr)     = v0;
        *(float4*)(cptr + 4) = v1;
    }
}

// ---------------- aggregation: one block (64 thr) per destination node -------
__global__ void k_aggregate() {
    int node = blockIdx.x;             // b*N + v
    int t = threadIdx.x;               // 0..63, each owns float4 of the 256-row
    int start = d_rowptr[node];
    int end   = d_rowptr[node + 1];
    int bBase = (node >> 12) << 12;    // b * N
    float4 acc = make_float4(0.f, 0.f, 0.f, 0.f);
    for (int j = start; j < end; j++) {
        int src = d_esrc[j];
        float w = d_eww[j];
        float4 x = __ldg((const float4*)&d_m[(size_t)(bBase + src) * Dd] + t);
        acc.x += w * x.x; acc.y += w * x.y; acc.z += w * x.z; acc.w += w * x.w;
    }
    ((float4*)&d_agg[(size_t)node * Dd])[t] = acc;
}

// ---------------- GRU gates + output mask ------------------------------------
__device__ __forceinline__ float sigmoidf_(float x) {
    return 1.0f / (1.0f + __expf(-x));
}

__global__ void k_gru(const float* __restrict__ h, const int* __restrict__ mask,
                      float* __restrict__ out) {
    int idx = blockIdx.x * blockDim.x + threadIdx.x;   // NODES*64
    if (idx >= NODES * 64) return;
    int row = idx >> 6;
    int c4  = idx & 63;
    const float4* gi = (const float4*)&d_gi[(size_t)row * G3D];
    const float4* gh = (const float4*)&d_gh[(size_t)row * G3D];
    float4 gir = gi[c4],        ghr = gh[c4];
    float4 giz = gi[64 + c4],   ghz = gh[64 + c4];
    float4 gin = gi[128 + c4],  ghn = gh[128 + c4];
    float4 hv  = ((const float4*)(h + (size_t)row * Dd))[c4];
    float valid = (mask[row] > 0) ? 1.0f : 0.0f;

    float4 o;
    {
        float r = sigmoidf_(gir.x + ghr.x);
        float z = sigmoidf_(giz.x + ghz.x);
        float n = tanhf(gin.x + r * ghn.x);
        o.x = ((1.0f - z) * n + z * hv.x) * valid;
    }
    {
        float r = sigmoidf_(gir.y + ghr.y);
        float z = sigmoidf_(giz.y + ghz.y);
        float n = tanhf(gin.y + r * ghn.y);
        o.y = ((1.0f - z) * n + z * hv.y) * valid;
    }
    {
        float r = sigmoidf_(gir.z + ghr.z);
        float z = sigmoidf_(giz.z + ghz.z);
        float n = tanhf(gin.z + r * ghn.z);
        o.z = ((1.0f - z) * n + z * hv.z) * valid;
    }
    {
        float r = sigmoidf_(gir.w + ghr.w);
        float z = sigmoidf_(giz.w + ghz.w);
        float n = tanhf(gin.w + r * ghn.w);
        o.w = ((1.0f - z) * n + z * hv.w) * valid;
    }
    ((float4*)(out + (size_t)row * Dd))[c4] = o;
}

// ---------------- launch ------------------------------------------------------
extern "C" void kernel_launch(void* const* d_in, const int* in_sizes, int n_in,
                              void* d_out, int out_size) {
    const float* x    = (const float*)d_in[0];   // [B,N,D]
    const int*   ei   = (const int*)  d_in[1];   // [B,2,E]
    const float* ew   = (const float*)d_in[2];   // [B,E]
    const int*   mask = (const int*)  d_in[3];   // [B,N]
    const float* W    = (const float*)d_in[4];   // [1,D,D]
    const float* Wih  = (const float*)d_in[5];   // [3D,D]
    const float* Whh  = (const float*)d_in[6];   // [3D,D]
    const float* bih  = (const float*)d_in[7];   // [3D]
    const float* bhh  = (const float*)d_in[8];   // [3D]
    float* out = (float*)d_out;

    float *p_m, *p_agg, *p_gi, *p_gh, *p_wiht, *p_whht;
    cudaGetSymbolAddress((void**)&p_m,    d_m);
    cudaGetSymbolAddress((void**)&p_agg,  d_agg);
    cudaGetSymbolAddress((void**)&p_gi,   d_gi);
    cudaGetSymbolAddress((void**)&p_gh,   d_gh);
    cudaGetSymbolAddress((void**)&p_wiht, d_WihT);
    cudaGetSymbolAddress((void**)&p_whht, d_WhhT);

    // CSR build
    k_zero<<<(NODES + 255) / 256, 256>>>();
    k_count<<<EDGES / 256, 256>>>(ei, mask);
    k_scan<<<1, 1024>>>();
    k_fill<<<EDGES / 256, 256>>>(ei, mask, ew);

    // weight transposes
    k_transpose<<<(G3D * Dd + 255) / 256, 256>>>(Wih, Whh);

    // m = x @ W
    {
        dim3 grid(Dd / 128, NODES / 128);   // (2, 256)
        sgemm_128x128<<<grid, 256>>>(x, W, p_m, nullptr, NODES, Dd, Dd);
    }

    // agg = segment_sum(m[u] * w, v)
    k_aggregate<<<NODES, 64>>>();

    // gi = agg @ WihT + bih ; gh = x @ WhhT + bhh
    {
        dim3 grid(G3D / 128, NODES / 128);  // (6, 256)
        sgemm_128x128<<<grid, 256>>>(p_agg, p_wiht, p_gi, bih, NODES, G3D, Dd);
        sgemm_128x128<<<grid, 256>>>(x, p_whht, p_gh, bhh, NODES, G3D, Dd);
    }

    // GRU + output mask
    k_gru<<<NODES * 64 / 256, 256>>>(x, mask, out);
}

// round 3
// speedup vs baseline: 1.9039x; 1.9039x over previous
#include <cuda_runtime.h>
#include <cuda_bf16.h>
#include <math.h>
#include <cstdint>

#define Bb 8
#define Nn 4096
#define Dd 256
#define Ee 65536
#define NODES (Bb * Nn)        // 32768
#define EDGES (Bb * Ee)        // 524288
#define G3D   (3 * Dd)         // 768

// ---------------- scratch (static device globals; no allocation) -------------
__device__ float d_m[NODES * Dd];          // x @ W
__device__ float d_agg[NODES * Dd];        // segment-summed messages
__device__ float d_gi[NODES * G3D];        // agg @ W_ih^T + b_ih
__device__ float d_gh[NODES * G3D];        // x   @ W_hh^T + b_hh
__device__ float d_Wt[Dd * Dd];            // W transposed -> [n][k]
__device__ int   d_counts[NODES];
__device__ int   d_cursor[NODES];
__device__ int   d_rowptr[NODES + 1];
__device__ int   d_esrc[EDGES];
__device__ float d_eww[EDGES];

// ---------------- CSR construction -------------------------------------------
__global__ void k_zero() {
    int i = blockIdx.x * blockDim.x + threadIdx.x;
    if (i < NODES) { d_counts[i] = 0; d_cursor[i] = 0; }
}

__global__ void k_count(const int* __restrict__ ei, const int* __restrict__ mask) {
    int idx = blockIdx.x * blockDim.x + threadIdx.x;
    if (idx >= EDGES) return;
    int b = idx >> 16;
    int e = idx & (Ee - 1);
    int u = ei[((b << 1) + 0) * Ee + e];
    int v = ei[((b << 1) + 1) * Ee + e];
    if (mask[(b << 12) + u] > 0 && mask[(b << 12) + v] > 0)
        atomicAdd(&d_counts[(b << 12) + v], 1);
}

__global__ void k_scan() {
    __shared__ int sums[1024];
    int t = threadIdx.x;
    int base = t * 32;
    int s = 0;
    #pragma unroll
    for (int i = 0; i < 32; i++) s += d_counts[base + i];
    sums[t] = s;
    __syncthreads();
    for (int off = 1; off < 1024; off <<= 1) {
        int v = (t >= off) ? sums[t - off] : 0;
        __syncthreads();
        sums[t] += v;
        __syncthreads();
    }
    int run = (t == 0) ? 0 : sums[t - 1];
    #pragma unroll
    for (int i = 0; i < 32; i++) {
        d_rowptr[base + i] = run;
        run += d_counts[base + i];
    }
    if (t == 1023) d_rowptr[NODES] = sums[1023];
}

__global__ void k_fill(const int* __restrict__ ei, const int* __restrict__ mask,
                       const float* __restrict__ ew) {
    int idx = blockIdx.x * blockDim.x + threadIdx.x;
    if (idx >= EDGES) return;
    int b = idx >> 16;
    int e = idx & (Ee - 1);
    int u = ei[((b << 1) + 0) * Ee + e];
    int v = ei[((b << 1) + 1) * Ee + e];
    if (mask[(b << 12) + u] > 0 && mask[(b << 12) + v] > 0) {
        int node = (b << 12) + v;
        int pos = d_rowptr[node] + atomicAdd(&d_cursor[node], 1);
        d_esrc[pos] = u;
        d_eww[pos]  = ew[idx];
    }
}

// ---------------- W transpose: [256,256] k-major -> n-major -------------------
__global__ void k_transposeW(const float* __restrict__ W) {
    int idx = blockIdx.x * blockDim.x + threadIdx.x;   // 65536
    if (idx >= Dd * Dd) return;
    int k = idx >> 8;
    int n = idx & 255;
    d_Wt[n * Dd + k] = W[idx];    // W[k][n] -> Wt[n][k]
}

// ---------------- mma.sync helpers --------------------------------------------
__device__ __forceinline__ uint32_t cvta_s(const void* p) {
    return (uint32_t)__cvta_generic_to_shared(p);
}

__device__ __forceinline__ void ldsm_x4(uint32_t& r0, uint32_t& r1, uint32_t& r2, uint32_t& r3,
                                        uint32_t addr) {
    asm volatile("ldmatrix.sync.aligned.m8n8.x4.shared.b16 {%0,%1,%2,%3}, [%4];"
                 : "=r"(r0), "=r"(r1), "=r"(r2), "=r"(r3) : "r"(addr));
}
__device__ __forceinline__ void ldsm_x2(uint32_t& r0, uint32_t& r1, uint32_t addr) {
    asm volatile("ldmatrix.sync.aligned.m8n8.x2.shared.b16 {%0,%1}, [%2];"
                 : "=r"(r0), "=r"(r1) : "r"(addr));
}

__device__ __forceinline__ void mma_bf16(float* d, const uint32_t* a, const uint32_t* b) {
    asm volatile(
        "mma.sync.aligned.m16n8k16.row.col.f32.bf16.bf16.f32 "
        "{%0,%1,%2,%3}, {%4,%5,%6,%7}, {%8,%9}, {%0,%1,%2,%3};"
        : "+f"(d[0]), "+f"(d[1]), "+f"(d[2]), "+f"(d[3])
        : "r"(a[0]), "r"(a[1]), "r"(a[2]), "r"(a[3]), "r"(b[0]), "r"(b[1]));
}

// ---------------- bf16x2-split GEMM: C[M,N] = A[M,K] * B[N,K]^T (+bias) ------
// BM=128, BN=128, BK=32, 256 threads (8 warps, 2x4 warp grid, 64x32 warp tile).
#define SPAD 40   // smem row stride in halves (80 B, conflict-free mod 128)

__global__ __launch_bounds__(256) void gemm_bf16x2(
    const float* __restrict__ A, const float* __restrict__ Bm,
    float* __restrict__ C, const float* __restrict__ bias,
    int N, int K)
{
    __shared__ __align__(16) __nv_bfloat16 As[2][128][SPAD];   // [hi/lo][row][k]
    __shared__ __align__(16) __nv_bfloat16 Bs[2][128][SPAD];

    const int t    = threadIdx.x;
    const int wid  = t >> 5;
    const int lane = t & 31;
    const int wm   = wid >> 2;        // 0..1
    const int wn   = wid & 3;         // 0..3
    const int m0   = blockIdx.y * 128;
    const int n0   = blockIdx.x * 128;

    // loader mapping: float4 g = t + i*256; row = g/8, c4 = g%8
    const int lrow = t >> 3;          // base row for i=0 (0..31), +32 per i
    const int lc4  = t & 7;

    float acc[4][4][4];
    #pragma unroll
    for (int mf = 0; mf < 4; mf++)
        #pragma unroll
        for (int nf = 0; nf < 4; nf++)
            #pragma unroll
            for (int j = 0; j < 4; j++) acc[mf][nf][j] = 0.0f;

    const int nchunks = K >> 5;       // 8

    float4 ra[4], rb[4];
    // prologue: load chunk 0
    #pragma unroll
    for (int i = 0; i < 4; i++) {
        int row = lrow + i * 32;
        ra[i] = __ldg((const float4*)(A + (size_t)(m0 + row) * K) + lc4);
        rb[i] = __ldg((const float4*)(Bm + (size_t)(n0 + row) * K) + lc4);
    }

    for (int kc = 0; kc < nchunks; kc++) {
        // split into hi/lo bf16 and store to smem
        #pragma unroll
        for (int i = 0; i < 4; i++) {
            int row = lrow + i * 32;
            float4 a = ra[i];
            __nv_bfloat162 ah0 = __floats2bfloat162_rn(a.x, a.y);
            __nv_bfloat162 ah1 = __floats2bfloat162_rn(a.z, a.w);
            __nv_bfloat162 al0 = __floats2bfloat162_rn(a.x - __bfloat162float(__low2bfloat16(ah0)),
                                                       a.y - __bfloat162float(__high2bfloat16(ah0)));
            __nv_bfloat162 al1 = __floats2bfloat162_rn(a.z - __bfloat162float(__low2bfloat16(ah1)),
                                                       a.w - __bfloat162float(__high2bfloat16(ah1)));
            *(__nv_bfloat162*)&As[0][row][lc4 * 4]     = ah0;
            *(__nv_bfloat162*)&As[0][row][lc4 * 4 + 2] = ah1;
            *(__nv_bfloat162*)&As[1][row][lc4 * 4]     = al0;
            *(__nv_bfloat162*)&As[1][row][lc4 * 4 + 2] = al1;

            float4 b = rb[i];
            __nv_bfloat162 bh0 = __floats2bfloat162_rn(b.x, b.y);
            __nv_bfloat162 bh1 = __floats2bfloat162_rn(b.z, b.w);
            __nv_bfloat162 bl0 = __floats2bfloat162_rn(b.x - __bfloat162float(__low2bfloat16(bh0)),
                                                       b.y - __bfloat162float(__high2bfloat16(bh0)));
            __nv_bfloat162 bl1 = __floats2bfloat162_rn(b.z - __bfloat162float(__low2bfloat16(bh1)),
                                                       b.w - __bfloat162float(__high2bfloat16(bh1)));
            *(__nv_bfloat162*)&Bs[0][row][lc4 * 4]     = bh0;
            *(__nv_bfloat162*)&Bs[0][row][lc4 * 4 + 2] = bh1;
            *(__nv_bfloat162*)&Bs[1][row][lc4 * 4]     = bl0;
            *(__nv_bfloat162*)&Bs[1][row][lc4 * 4 + 2] = bl1;
        }
        __syncthreads();

        // prefetch next chunk while MMAs run
        if (kc + 1 < nchunks) {
            #pragma unroll
            for (int i = 0; i < 4; i++) {
                int row = lrow + i * 32;
                ra[i] = __ldg((const float4*)(A + (size_t)(m0 + row) * K + (kc + 1) * 32) + lc4);
                rb[i] = __ldg((const float4*)(Bm + (size_t)(n0 + row) * K + (kc + 1) * 32) + lc4);
            }
        }

        #pragma unroll
        for (int ks = 0; ks < 2; ks++) {
            const int k0 = ks * 16;
            uint32_t ahi[4][4], alo[4][4], bhi[4][2], blo[4][2];
            #pragma unroll
            for (int mf = 0; mf < 4; mf++) {
                int arow = wm * 64 + mf * 16 + (lane & 15);
                int acol = k0 + ((lane >> 4) & 1) * 8;
                ldsm_x4(ahi[mf][0], ahi[mf][1], ahi[mf][2], ahi[mf][3],
                        cvta_s(&As[0][arow][acol]));
                ldsm_x4(alo[mf][0], alo[mf][1], alo[mf][2], alo[mf][3],
                        cvta_s(&As[1][arow][acol]));
            }
            #pragma unroll
            for (int nf = 0; nf < 4; nf++) {
                int brow = wn * 32 + nf * 8 + (lane & 7);
                int bcol = k0 + ((lane >> 3) & 1) * 8;
                ldsm_x2(bhi[nf][0], bhi[nf][1], cvta_s(&Bs[0][brow][bcol]));
                ldsm_x2(blo[nf][0], blo[nf][1], cvta_s(&Bs[1][brow][bcol]));
            }
            #pragma unroll
            for (int mf = 0; mf < 4; mf++)
                #pragma unroll
                for (int nf = 0; nf < 4; nf++) {
                    mma_bf16(acc[mf][nf], ahi[mf], bhi[nf]);
                    mma_bf16(acc[mf][nf], alo[mf], bhi[nf]);
                    mma_bf16(acc[mf][nf], ahi[mf], blo[nf]);
                }
        }
        __syncthreads();
    }

    // epilogue: d frag layout -> rows (l/4, l/4+8), cols (l%4)*2, +1
    const int erow = (lane >> 2);
    const int ecol = (lane & 3) * 2;
    #pragma unroll
    for (int mf = 0; mf < 4; mf++) {
        #pragma unroll
        for (int nf = 0; nf < 4; nf++) {
            int r0 = m0 + wm * 64 + mf * 16 + erow;
            int c0 = n0 + wn * 32 + nf * 8 + ecol;
            float b0 = 0.f, b1 = 0.f;
            if (bias) { b0 = bias[c0]; b1 = bias[c0 + 1]; }
            float2 v0 = make_float2(acc[mf][nf][0] + b0, acc[mf][nf][1] + b1);
            float2 v1 = make_float2(acc[mf][nf][2] + b0, acc[mf][nf][3] + b1);
            *(float2*)(C + (size_t)r0 * N + c0)       = v0;
            *(float2*)(C + (size_t)(r0 + 8) * N + c0) = v1;
        }
    }
}

// ---------------- aggregation: one block (64 thr) per destination node -------
__global__ void k_aggregate() {
    int node = blockIdx.x;
    int t = threadIdx.x;
    int start = d_rowptr[node];
    int end   = d_rowptr[node + 1];
    int bBase = (node >> 12) << 12;
    float4 acc = make_float4(0.f, 0.f, 0.f, 0.f);
    for (int j = start; j < end; j++) {
        int src = d_esrc[j];
        float w = d_eww[j];
        float4 x = __ldg((const float4*)&d_m[(size_t)(bBase + src) * Dd] + t);
        acc.x += w * x.x; acc.y += w * x.y; acc.z += w * x.z; acc.w += w * x.w;
    }
    ((float4*)&d_agg[(size_t)node * Dd])[t] = acc;
}

// ---------------- GRU gates + output mask ------------------------------------
__device__ __forceinline__ float sigmoidf_(float x) {
    return 1.0f / (1.0f + __expf(-x));
}

__global__ void k_gru(const float* __restrict__ h, const int* __restrict__ mask,
                      float* __restrict__ out) {
    int idx = blockIdx.x * blockDim.x + threadIdx.x;
    if (idx >= NODES * 64) return;
    int row = idx >> 6;
    int c4  = idx & 63;
    const float4* gi = (const float4*)&d_gi[(size_t)row * G3D];
    const float4* gh = (const float4*)&d_gh[(size_t)row * G3D];
    float4 gir = gi[c4],        ghr = gh[c4];
    float4 giz = gi[64 + c4],   ghz = gh[64 + c4];
    float4 gin = gi[128 + c4],  ghn = gh[128 + c4];
    float4 hv  = ((const float4*)(h + (size_t)row * Dd))[c4];
    float valid = (mask[row] > 0) ? 1.0f : 0.0f;

    float4 o;
    {
        float r = sigmoidf_(gir.x + ghr.x);
        float z = sigmoidf_(giz.x + ghz.x);
        float n = tanhf(gin.x + r * ghn.x);
        o.x = ((1.0f - z) * n + z * hv.x) * valid;
    }
    {
        float r = sigmoidf_(gir.y + ghr.y);
        float z = sigmoidf_(giz.y + ghz.y);
        float n = tanhf(gin.y + r * ghn.y);
        o.y = ((1.0f - z) * n + z * hv.y) * valid;
    }
    {
        float r = sigmoidf_(gir.z + ghr.z);
        float z = sigmoidf_(giz.z + ghz.z);
        float n = tanhf(gin.z + r * ghn.z);
        o.z = ((1.0f - z) * n + z * hv.z) * valid;
    }
    {
        float r = sigmoidf_(gir.w + ghr.w);
        float z = sigmoidf_(giz.w + ghz.w);
        float n = tanhf(gin.w + r * ghn.w);
        o.w = ((1.0f - z) * n + z * hv.w) * valid;
    }
    ((float4*)(out + (size_t)row * Dd))[c4] = o;
}

// ---------------- launch ------------------------------------------------------
extern "C" void kernel_launch(void* const* d_in, const int* in_sizes, int n_in,
                              void* d_out, int out_size) {
    const float* x    = (const float*)d_in[0];   // [B,N,D]
    const int*   ei   = (const int*)  d_in[1];   // [B,2,E]
    const float* ew   = (const float*)d_in[2];   // [B,E]
    const int*   mask = (const int*)  d_in[3];   // [B,N]
    const float* W    = (const float*)d_in[4];   // [1,D,D]
    const float* Wih  = (const float*)d_in[5];   // [3D,D] == B[n][k]
    const float* Whh  = (const float*)d_in[6];   // [3D,D]
    const float* bih  = (const float*)d_in[7];   // [3D]
    const float* bhh  = (const float*)d_in[8];   // [3D]
    float* out = (float*)d_out;

    float *p_m, *p_agg, *p_gi, *p_gh, *p_wt;
    cudaGetSymbolAddress((void**)&p_m,   d_m);
    cudaGetSymbolAddress((void**)&p_agg, d_agg);
    cudaGetSymbolAddress((void**)&p_gi,  d_gi);
    cudaGetSymbolAddress((void**)&p_gh,  d_gh);
    cudaGetSymbolAddress((void**)&p_wt,  d_Wt);

    // CSR build
    k_zero<<<(NODES + 255) / 256, 256>>>();
    k_count<<<EDGES / 256, 256>>>(ei, mask);
    k_scan<<<1, 1024>>>();
    k_fill<<<EDGES / 256, 256>>>(ei, mask, ew);

    // W transpose (B[n][k] = W[k][n])
    k_transposeW<<<(Dd * Dd + 255) / 256, 256>>>(W);

    // m = x @ W
    {
        dim3 grid(Dd / 128, NODES / 128);   // (2, 256)
        gemm_bf16x2<<<grid, 256>>>(x, p_wt, p_m, nullptr, Dd, Dd);
    }

    // agg = segment_sum(m[u] * w, v)
    k_aggregate<<<NODES, 64>>>();

    // gi = agg @ Wih^T + bih ; gh = x @ Whh^T + bhh
    {
        dim3 grid(G3D / 128, NODES / 128);  // (6, 256)
        gemm_bf16x2<<<grid, 256>>>(p_agg, Wih, p_gi, bih, G3D, Dd);
        gemm_bf16x2<<<grid, 256>>>(x, Whh, p_gh, bhh, G3D, Dd);
    }

    // GRU + output mask
    k_gru<<<NODES * 64 / 256, 256>>>(x, mask, out);
}

// round 4
// speedup vs baseline: 2.0345x; 1.0686x over previous
#include <cuda_runtime.h>
#include <cuda_bf16.h>
#include <math.h>
#include <cstdint>

#define Bb 8
#define Nn 4096
#define Dd 256
#define Ee 65536
#define NODES (Bb * Nn)        // 32768
#define EDGES (Bb * Ee)        // 524288
#define G3D   (3 * Dd)         // 768

// ---------------- scratch (static device globals; no allocation) -------------
__device__ float d_m[NODES * Dd];                  // x @ W (fp32)
__device__ float d_gi[NODES * G3D];
__device__ float d_gh[NODES * G3D];
__device__ __nv_bfloat16 d_xhi[NODES * Dd];
__device__ __nv_bfloat16 d_xlo[NODES * Dd];
__device__ __nv_bfloat16 d_agghi[NODES * Dd];
__device__ __nv_bfloat16 d_agglo[NODES * Dd];
__device__ __nv_bfloat16 d_Wthi[Dd * Dd];
__device__ __nv_bfloat16 d_Wtlo[Dd * Dd];
__device__ __nv_bfloat16 d_Wihhi[G3D * Dd];
__device__ __nv_bfloat16 d_Wihlo[G3D * Dd];
__device__ __nv_bfloat16 d_Whhhi[G3D * Dd];
__device__ __nv_bfloat16 d_Whhlo[G3D * Dd];
__device__ int   d_counts[NODES];
__device__ int   d_cursor[NODES];
__device__ int   d_rowptr[NODES + 1];
__device__ int   d_esrc[EDGES];
__device__ float d_eww[EDGES];

// ---------------- CSR construction -------------------------------------------
__global__ void k_zero() {
    int i = blockIdx.x * blockDim.x + threadIdx.x;
    if (i < NODES) { d_counts[i] = 0; d_cursor[i] = 0; }
}

__global__ void k_count(const int* __restrict__ ei, const int* __restrict__ mask) {
    int idx = blockIdx.x * blockDim.x + threadIdx.x;
    if (idx >= EDGES) return;
    int b = idx >> 16;
    int e = idx & (Ee - 1);
    int u = ei[((b << 1) + 0) * Ee + e];
    int v = ei[((b << 1) + 1) * Ee + e];
    if (mask[(b << 12) + u] > 0 && mask[(b << 12) + v] > 0)
        atomicAdd(&d_counts[(b << 12) + v], 1);
}

__global__ void k_scan() {
    __shared__ int sums[1024];
    int t = threadIdx.x;
    int base = t * 32;
    int s = 0;
    #pragma unroll
    for (int i = 0; i < 32; i++) s += d_counts[base + i];
    sums[t] = s;
    __syncthreads();
    for (int off = 1; off < 1024; off <<= 1) {
        int v = (t >= off) ? sums[t - off] : 0;
        __syncthreads();
        sums[t] += v;
        __syncthreads();
    }
    int run = (t == 0) ? 0 : sums[t - 1];
    #pragma unroll
    for (int i = 0; i < 32; i++) {
        d_rowptr[base + i] = run;
        run += d_counts[base + i];
    }
    if (t == 1023) d_rowptr[NODES] = sums[1023];
}

__global__ void k_fill(const int* __restrict__ ei, const int* __restrict__ mask,
                       const float* __restrict__ ew) {
    int idx = blockIdx.x * blockDim.x + threadIdx.x;
    if (idx >= EDGES) return;
    int b = idx >> 16;
    int e = idx & (Ee - 1);
    int u = ei[((b << 1) + 0) * Ee + e];
    int v = ei[((b << 1) + 1) * Ee + e];
    if (mask[(b << 12) + u] > 0 && mask[(b << 12) + v] > 0) {
        int node = (b << 12) + v;
        int pos = d_rowptr[node] + atomicAdd(&d_cursor[node], 1);
        d_esrc[pos] = u;
        d_eww[pos]  = ew[idx];
    }
}

// ---------------- split helpers -----------------------------------------------
__device__ __forceinline__ void split2(float a, float b, __nv_bfloat162& hi, __nv_bfloat162& lo) {
    hi = __floats2bfloat162_rn(a, b);
    lo = __floats2bfloat162_rn(a - __bfloat162float(__low2bfloat16(hi)),
                               b - __bfloat162float(__high2bfloat16(hi)));
}

// split x: [NODES*Dd] floats -> hi/lo bf16
__global__ void k_split_x(const float* __restrict__ x) {
    int idx = blockIdx.x * blockDim.x + threadIdx.x;   // NODES*Dd/2
    if (idx >= NODES * Dd / 2) return;
    float2 v = ((const float2*)x)[idx];
    __nv_bfloat162 h, l;
    split2(v.x, v.y, h, l);
    ((__nv_bfloat162*)d_xhi)[idx] = h;
    ((__nv_bfloat162*)d_xlo)[idx] = l;
}

// split Wih/Whh: [G3D*Dd] each
__global__ void k_split_w(const float* __restrict__ wih, const float* __restrict__ whh) {
    int idx = blockIdx.x * blockDim.x + threadIdx.x;   // G3D*Dd/2
    if (idx >= G3D * Dd / 2) return;
    float2 a = ((const float2*)wih)[idx];
    __nv_bfloat162 h, l;
    split2(a.x, a.y, h, l);
    ((__nv_bfloat162*)d_Wihhi)[idx] = h;
    ((__nv_bfloat162*)d_Wihlo)[idx] = l;
    float2 b = ((const float2*)whh)[idx];
    split2(b.x, b.y, h, l);
    ((__nv_bfloat162*)d_Whhhi)[idx] = h;
    ((__nv_bfloat162*)d_Whhlo)[idx] = l;
}

// transpose + split W: Wt[n][k] = W[k][n]
__global__ void k_transpose_split_W(const float* __restrict__ W) {
    int idx = blockIdx.x * blockDim.x + threadIdx.x;   // Dd*Dd/2 (two k per thread)
    if (idx >= Dd * Dd / 2) return;
    int n  = idx >> 7;          // 0..255
    int k2 = idx & 127;         // pair index along k
    float a = W[(k2 * 2 + 0) * Dd + n];
    float b = W[(k2 * 2 + 1) * Dd + n];
    __nv_bfloat162 h, l;
    split2(a, b, h, l);
    ((__nv_bfloat162*)d_Wthi)[n * (Dd / 2) + k2] = h;
    ((__nv_bfloat162*)d_Wtlo)[n * (Dd / 2) + k2] = l;
}

// ---------------- mma.sync helpers --------------------------------------------
__device__ __forceinline__ uint32_t cvta_s(const void* p) {
    return (uint32_t)__cvta_generic_to_shared(p);
}

__device__ __forceinline__ void ldsm_x4(uint32_t& r0, uint32_t& r1, uint32_t& r2, uint32_t& r3,
                                        uint32_t addr) {
    asm volatile("ldmatrix.sync.aligned.m8n8.x4.shared.b16 {%0,%1,%2,%3}, [%4];"
                 : "=r"(r0), "=r"(r1), "=r"(r2), "=r"(r3) : "r"(addr));
}
__device__ __forceinline__ void ldsm_x2(uint32_t& r0, uint32_t& r1, uint32_t addr) {
    asm volatile("ldmatrix.sync.aligned.m8n8.x2.shared.b16 {%0,%1}, [%2];"
                 : "=r"(r0), "=r"(r1) : "r"(addr));
}

__device__ __forceinline__ void mma_bf16(float* d, const uint32_t* a, const uint32_t* b) {
    asm volatile(
        "mma.sync.aligned.m16n8k16.row.col.f32.bf16.bf16.f32 "
        "{%0,%1,%2,%3}, {%4,%5,%6,%7}, {%8,%9}, {%0,%1,%2,%3};"
        : "+f"(d[0]), "+f"(d[1]), "+f"(d[2]), "+f"(d[3])
        : "r"(a[0]), "r"(a[1]), "r"(a[2]), "r"(a[3]), "r"(b[0]), "r"(b[1]));
}

#define CP16(dst, src) \
    asm volatile("cp.async.cg.shared.global [%0], [%1], 16;" :: "r"(dst), "l"(src))
#define CP_COMMIT() asm volatile("cp.async.commit_group;" ::: "memory")

// ---------------- pre-split bf16 GEMM: C = A * B^T (+bias) -------------------
// BM=128, BN=128, BK=32, 256 threads (8 warps, 2x4 grid, 64x32 warp tiles).
// cp.async 2-stage pipeline; A/B already split into hi/lo bf16, K-major.
#define SPAD 40                         // halves per smem row (80 B)
#define ARR_BYTES (128 * SPAD * 2)      // 10240
#define STAGE_BYTES (4 * ARR_BYTES)     // 40960
#define GEMM_SMEM (2 * STAGE_BYTES)     // 81920

__global__ __launch_bounds__(256, 2) void gemm_pre(
    const __nv_bfloat16* __restrict__ Ahi, const __nv_bfloat16* __restrict__ Alo,
    const __nv_bfloat16* __restrict__ Bhi, const __nv_bfloat16* __restrict__ Blo,
    float* __restrict__ C, const float* __restrict__ bias,
    int N, int K)
{
    extern __shared__ char smem[];
    const uint32_t sb = cvta_s(smem);
    const int t    = threadIdx.x;
    const int wid  = t >> 5;
    const int lane = t & 31;
    const int wm   = wid >> 2;
    const int wn   = wid & 3;
    const int m0   = blockIdx.y * 128;
    const int n0   = blockIdx.x * 128;

    // loader: chunk c = t + i*256 (i=0..1); row = c>>2 (0..127), c4 = c&3
    const int lrow = t >> 2;
    const int lc4  = t & 3;

    float acc[4][4][4];
    #pragma unroll
    for (int mf = 0; mf < 4; mf++)
        #pragma unroll
        for (int nf = 0; nf < 4; nf++)
            #pragma unroll
            for (int j = 0; j < 4; j++) acc[mf][nf][j] = 0.0f;

    const int nchunks = K >> 5;   // 8

    auto load_stage = [&](int kc, int s) {
        uint32_t base = sb + s * STAGE_BYTES;
        #pragma unroll
        for (int i = 0; i < 2; i++) {
            int row = lrow + i * 64;
            uint32_t doff = (uint32_t)(row * (SPAD * 2) + lc4 * 16);
            size_t asrc = (size_t)(m0 + row) * K + kc * 32 + lc4 * 8;
            size_t bsrc = (size_t)(n0 + row) * K + kc * 32 + lc4 * 8;
            CP16(base + 0 * ARR_BYTES + doff, Ahi + asrc);
            CP16(base + 1 * ARR_BYTES + doff, Alo + asrc);
            CP16(base + 2 * ARR_BYTES + doff, Bhi + bsrc);
            CP16(base + 3 * ARR_BYTES + doff, Blo + bsrc);
        }
        CP_COMMIT();
    };

    load_stage(0, 0);

    for (int kc = 0; kc < nchunks; kc++) {
        const int s = kc & 1;
        if (kc + 1 < nchunks) {
            load_stage(kc + 1, s ^ 1);
            asm volatile("cp.async.wait_group 1;" ::: "memory");
        } else {
            asm volatile("cp.async.wait_group 0;" ::: "memory");
        }
        __syncthreads();

        const uint32_t base = sb + s * STAGE_BYTES;
        #pragma unroll
        for (int ks = 0; ks < 2; ks++) {
            const int k0 = ks * 16;
            uint32_t ahi[4][4], alo[4][4], bhi[4][2], blo[4][2];
            #pragma unroll
            for (int mf = 0; mf < 4; mf++) {
                int arow = wm * 64 + mf * 16 + (lane & 15);
                int acol = k0 + ((lane >> 4) & 1) * 8;
                uint32_t ao = (uint32_t)((arow * SPAD + acol) * 2);
                ldsm_x4(ahi[mf][0], ahi[mf][1], ahi[mf][2], ahi[mf][3], base + 0 * ARR_BYTES + ao);
                ldsm_x4(alo[mf][0], alo[mf][1], alo[mf][2], alo[mf][3], base + 1 * ARR_BYTES + ao);
            }
            #pragma unroll
            for (int nf = 0; nf < 4; nf++) {
                int brow = wn * 32 + nf * 8 + (lane & 7);
                int bcol = k0 + ((lane >> 3) & 1) * 8;
                uint32_t bo = (uint32_t)((brow * SPAD + bcol) * 2);
                ldsm_x2(bhi[nf][0], bhi[nf][1], base + 2 * ARR_BYTES + bo);
                ldsm_x2(blo[nf][0], blo[nf][1], base + 3 * ARR_BYTES + bo);
            }
            #pragma unroll
            for (int mf = 0; mf < 4; mf++)
                #pragma unroll
                for (int nf = 0; nf < 4; nf++) {
                    mma_bf16(acc[mf][nf], ahi[mf], bhi[nf]);
                    mma_bf16(acc[mf][nf], alo[mf], bhi[nf]);
                    mma_bf16(acc[mf][nf], ahi[mf], blo[nf]);
                }
        }
        __syncthreads();
    }

    // epilogue
    const int erow = (lane >> 2);
    const int ecol = (lane & 3) * 2;
    #pragma unroll
    for (int mf = 0; mf < 4; mf++) {
        #pragma unroll
        for (int nf = 0; nf < 4; nf++) {
            int r0 = m0 + wm * 64 + mf * 16 + erow;
            int c0 = n0 + wn * 32 + nf * 8 + ecol;
            float b0 = 0.f, b1 = 0.f;
            if (bias) { b0 = bias[c0]; b1 = bias[c0 + 1]; }
            float2 v0 = make_float2(acc[mf][nf][0] + b0, acc[mf][nf][1] + b1);
            float2 v1 = make_float2(acc[mf][nf][2] + b0, acc[mf][nf][3] + b1);
            *(float2*)(C + (size_t)r0 * N + c0)       = v0;
            *(float2*)(C + (size_t)(r0 + 8) * N + c0) = v1;
        }
    }
}

// ---------------- aggregation: writes split bf16 agg directly ----------------
__global__ void k_aggregate() {
    int node = blockIdx.x;
    int t = threadIdx.x;               // 0..63, owns 4 floats of the 256-row
    int start = d_rowptr[node];
    int end   = d_rowptr[node + 1];
    int bBase = (node >> 12) << 12;
    float4 acc = make_float4(0.f, 0.f, 0.f, 0.f);
    for (int j = start; j < end; j++) {
        int src = d_esrc[j];
        float w = d_eww[j];
        float4 x = __ldg((const float4*)&d_m[(size_t)(bBase + src) * Dd] + t);
        acc.x += w * x.x; acc.y += w * x.y; acc.z += w * x.z; acc.w += w * x.w;
    }
    __nv_bfloat162 h0, l0, h1, l1;
    split2(acc.x, acc.y, h0, l0);
    split2(acc.z, acc.w, h1, l1);
    size_t o = (size_t)node * (Dd / 2) + t * 2;
    ((__nv_bfloat162*)d_agghi)[o]     = h0;
    ((__nv_bfloat162*)d_agghi)[o + 1] = h1;
    ((__nv_bfloat162*)d_agglo)[o]     = l0;
    ((__nv_bfloat162*)d_agglo)[o + 1] = l1;
}

// ---------------- GRU gates + output mask ------------------------------------
__device__ __forceinline__ float sigmoidf_(float x) {
    return 1.0f / (1.0f + __expf(-x));
}

__global__ void k_gru(const float* __restrict__ h, const int* __restrict__ mask,
                      float* __restrict__ out) {
    int idx = blockIdx.x * blockDim.x + threadIdx.x;
    if (idx >= NODES * 64) return;
    int row = idx >> 6;
    int c4  = idx & 63;
    const float4* gi = (const float4*)&d_gi[(size_t)row * G3D];
    const float4* gh = (const float4*)&d_gh[(size_t)row * G3D];
    float4 gir = gi[c4],        ghr = gh[c4];
    float4 giz = gi[64 + c4],   ghz = gh[64 + c4];
    float4 gin = gi[128 + c4],  ghn = gh[128 + c4];
    float4 hv  = ((const float4*)(h + (size_t)row * Dd))[c4];
    float valid = (mask[row] > 0) ? 1.0f : 0.0f;

    float4 o;
    {
        float r = sigmoidf_(gir.x + ghr.x);
        float z = sigmoidf_(giz.x + ghz.x);
        float n = tanhf(gin.x + r * ghn.x);
        o.x = ((1.0f - z) * n + z * hv.x) * valid;
    }
    {
        float r = sigmoidf_(gir.y + ghr.y);
        float z = sigmoidf_(giz.y + ghz.y);
        float n = tanhf(gin.y + r * ghn.y);
        o.y = ((1.0f - z) * n + z * hv.y) * valid;
    }
    {
        float r = sigmoidf_(gir.z + ghr.z);
        float z = sigmoidf_(giz.z + ghz.z);
        float n = tanhf(gin.z + r * ghn.z);
        o.z = ((1.0f - z) * n + z * hv.z) * valid;
    }
    {
        float r = sigmoidf_(gir.w + ghr.w);
        float z = sigmoidf_(giz.w + ghz.w);
        float n = tanhf(gin.w + r * ghn.w);
        o.w = ((1.0f - z) * n + z * hv.w) * valid;
    }
    ((float4*)(out + (size_t)row * Dd))[c4] = o;
}

// ---------------- launch ------------------------------------------------------
extern "C" void kernel_launch(void* const* d_in, const int* in_sizes, int n_in,
                              void* d_out, int out_size) {
    const float* x    = (const float*)d_in[0];
    const int*   ei   = (const int*)  d_in[1];
    const float* ew   = (const float*)d_in[2];
    const int*   mask = (const int*)  d_in[3];
    const float* W    = (const float*)d_in[4];
    const float* Wih  = (const float*)d_in[5];
    const float* Whh  = (const float*)d_in[6];
    const float* bih  = (const float*)d_in[7];
    const float* bhh  = (const float*)d_in[8];
    float* out = (float*)d_out;

    float *p_m, *p_gi, *p_gh;
    __nv_bfloat16 *p_xhi, *p_xlo, *p_agghi, *p_agglo;
    __nv_bfloat16 *p_wthi, *p_wtlo, *p_wihhi, *p_wihlo, *p_whhhi, *p_whhlo;
    cudaGetSymbolAddress((void**)&p_m,     d_m);
    cudaGetSymbolAddress((void**)&p_gi,    d_gi);
    cudaGetSymbolAddress((void**)&p_gh,    d_gh);
    cudaGetSymbolAddress((void**)&p_xhi,   d_xhi);
    cudaGetSymbolAddress((void**)&p_xlo,   d_xlo);
    cudaGetSymbolAddress((void**)&p_agghi, d_agghi);
    cudaGetSymbolAddress((void**)&p_agglo, d_agglo);
    cudaGetSymbolAddress((void**)&p_wthi,  d_Wthi);
    cudaGetSymbolAddress((void**)&p_wtlo,  d_Wtlo);
    cudaGetSymbolAddress((void**)&p_wihhi, d_Wihhi);
    cudaGetSymbolAddress((void**)&p_wihlo, d_Wihlo);
    cudaGetSymbolAddress((void**)&p_whhhi, d_Whhhi);
    cudaGetSymbolAddress((void**)&p_whhlo, d_Whhlo);

    cudaFuncSetAttribute(gemm_pre, cudaFuncAttributeMaxDynamicSharedMemorySize, GEMM_SMEM);

    // CSR build
    k_zero<<<(NODES + 255) / 256, 256>>>();
    k_count<<<EDGES / 256, 256>>>(ei, mask);
    k_scan<<<1, 1024>>>();
    k_fill<<<EDGES / 256, 256>>>(ei, mask, ew);

    // splits
    k_split_x<<<(NODES * Dd / 2 + 255) / 256, 256>>>(x);
    k_split_w<<<(G3D * Dd / 2 + 255) / 256, 256>>>(Wih, Whh);
    k_transpose_split_W<<<(Dd * Dd / 2 + 255) / 256, 256>>>(W);

    // m = x @ W
    {
        dim3 grid(Dd / 128, NODES / 128);   // (2, 256)
        gemm_pre<<<grid, 256, GEMM_SMEM>>>(p_xhi, p_xlo, p_wthi, p_wtlo, p_m, nullptr, Dd, Dd);
    }

    // agg (writes split bf16)
    k_aggregate<<<NODES, 64>>>();

    // gi = agg @ Wih^T + bih ; gh = x @ Whh^T + bhh
    {
        dim3 grid(G3D / 128, NODES / 128);  // (6, 256)
        gemm_pre<<<grid, 256, GEMM_SMEM>>>(p_agghi, p_agglo, p_wihhi, p_wihlo, p_gi, bih, G3D, Dd);
        gemm_pre<<<grid, 256, GEMM_SMEM>>>(p_xhi, p_xlo, p_whhhi, p_whhlo, p_gh, bhh, G3D, Dd);
    }

    // GRU + output mask
    k_gru<<<NODES * 64 / 256, 256>>>(x, mask, out);
}

// round 5
// speedup vs baseline: 2.1337x; 1.0487x over previous
#include <cuda_runtime.h>
#include <cuda_bf16.h>
#include <math.h>
#include <cstdint>

#define Bb 8
#define Nn 4096
#define Dd 256
#define Ee 65536
#define NODES (Bb * Nn)        // 32768
#define EDGES (Bb * Ee)        // 524288
#define G3D   (3 * Dd)         // 768

// ---------------- scratch (static device globals; no allocation) -------------
__device__ float d_gi[NODES * G3D];                // permuted-col layout
__device__ float d_Wct[G3D * Dd];                  // (Wih @ W^T), permuted rows
__device__ __nv_bfloat16 d_xhi[NODES * Dd];
__device__ __nv_bfloat16 d_xlo[NODES * Dd];
__device__ __nv_bfloat16 d_agghi[NODES * Dd];
__device__ __nv_bfloat16 d_agglo[NODES * Dd];
__device__ __nv_bfloat16 d_Whi[Dd * Dd];           // W plain split
__device__ __nv_bfloat16 d_Wlo[Dd * Dd];
__device__ __nv_bfloat16 d_Wihphi[G3D * Dd];       // Wih, rows permuted
__device__ __nv_bfloat16 d_Wihplo[G3D * Dd];
__device__ __nv_bfloat16 d_Whhphi[G3D * Dd];       // Whh, rows permuted
__device__ __nv_bfloat16 d_Whhplo[G3D * Dd];
__device__ __nv_bfloat16 d_Wcthi[G3D * Dd];
__device__ __nv_bfloat16 d_Wctlo[G3D * Dd];
__device__ float d_bihp[G3D];
__device__ float d_bhhp[G3D];
__device__ int   d_counts[NODES];
__device__ int   d_cursor[NODES];
__device__ int   d_rowptr[NODES + 1];
__device__ int   d_esrc[EDGES];
__device__ float d_eww[EDGES];

// permutation: orig row o = g*256+d  ->  o' = (d>>5)*96 + g*32 + (d&31)

// ---------------- CSR construction -------------------------------------------
__global__ void k_zero() {
    int i = blockIdx.x * blockDim.x + threadIdx.x;
    if (i < NODES) { d_counts[i] = 0; d_cursor[i] = 0; }
}

__global__ void k_count(const int* __restrict__ ei, const int* __restrict__ mask) {
    int idx = blockIdx.x * blockDim.x + threadIdx.x;
    if (idx >= EDGES) return;
    int b = idx >> 16;
    int e = idx & (Ee - 1);
    int u = ei[((b << 1) + 0) * Ee + e];
    int v = ei[((b << 1) + 1) * Ee + e];
    if (mask[(b << 12) + u] > 0 && mask[(b << 12) + v] > 0)
        atomicAdd(&d_counts[(b << 12) + v], 1);
}

__global__ void k_scan() {
    __shared__ int sums[1024];
    int t = threadIdx.x;
    int base = t * 32;
    int s = 0;
    #pragma unroll
    for (int i = 0; i < 32; i++) s += d_counts[base + i];
    sums[t] = s;
    __syncthreads();
    for (int off = 1; off < 1024; off <<= 1) {
        int v = (t >= off) ? sums[t - off] : 0;
        __syncthreads();
        sums[t] += v;
        __syncthreads();
    }
    int run = (t == 0) ? 0 : sums[t - 1];
    #pragma unroll
    for (int i = 0; i < 32; i++) {
        d_rowptr[base + i] = run;
        run += d_counts[base + i];
    }
    if (t == 1023) d_rowptr[NODES] = sums[1023];
}

__global__ void k_fill(const int* __restrict__ ei, const int* __restrict__ mask,
                       const float* __restrict__ ew) {
    int idx = blockIdx.x * blockDim.x + threadIdx.x;
    if (idx >= EDGES) return;
    int b = idx >> 16;
    int e = idx & (Ee - 1);
    int u = ei[((b << 1) + 0) * Ee + e];
    int v = ei[((b << 1) + 1) * Ee + e];
    if (mask[(b << 12) + u] > 0 && mask[(b << 12) + v] > 0) {
        int node = (b << 12) + v;
        int pos = d_rowptr[node] + atomicAdd(&d_cursor[node], 1);
        d_esrc[pos] = u;
        d_eww[pos]  = ew[idx];
    }
}

// ---------------- split helpers -----------------------------------------------
__device__ __forceinline__ void split2(float a, float b, __nv_bfloat162& hi, __nv_bfloat162& lo) {
    hi = __floats2bfloat162_rn(a, b);
    lo = __floats2bfloat162_rn(a - __bfloat162float(__low2bfloat16(hi)),
                               b - __bfloat162float(__high2bfloat16(hi)));
}

__global__ void k_split_x(const float* __restrict__ x) {
    int idx = blockIdx.x * blockDim.x + threadIdx.x;
    if (idx >= NODES * Dd / 2) return;
    float2 v = ((const float2*)x)[idx];
    __nv_bfloat162 h, l;
    split2(v.x, v.y, h, l);
    ((__nv_bfloat162*)d_xhi)[idx] = h;
    ((__nv_bfloat162*)d_xlo)[idx] = l;
}

__global__ void k_split_W(const float* __restrict__ W) {
    int idx = blockIdx.x * blockDim.x + threadIdx.x;
    if (idx >= Dd * Dd / 2) return;
    float2 v = ((const float2*)W)[idx];
    __nv_bfloat162 h, l;
    split2(v.x, v.y, h, l);
    ((__nv_bfloat162*)d_Whi)[idx] = h;
    ((__nv_bfloat162*)d_Wlo)[idx] = l;
}

// permuted-row split of Wih/Whh + permuted biases
__global__ void k_permsplit(const float* __restrict__ wih, const float* __restrict__ whh,
                            const float* __restrict__ bih, const float* __restrict__ bhh) {
    int idx = blockIdx.x * blockDim.x + threadIdx.x;   // G3D * Dd/2
    if (idx >= G3D * Dd / 2) return;
    int o    = idx / (Dd / 2);
    int col2 = idx - o * (Dd / 2);
    int g = o >> 8, d = o & 255;
    int op = (d >> 5) * 96 + g * 32 + (d & 31);
    size_t dst = (size_t)op * (Dd / 2) + col2;
    float2 a = ((const float2*)wih)[idx];
    __nv_bfloat162 h, l;
    split2(a.x, a.y, h, l);
    ((__nv_bfloat162*)d_Wihphi)[dst] = h;
    ((__nv_bfloat162*)d_Wihplo)[dst] = l;
    float2 b = ((const float2*)whh)[idx];
    split2(b.x, b.y, h, l);
    ((__nv_bfloat162*)d_Whhphi)[dst] = h;
    ((__nv_bfloat162*)d_Whhplo)[dst] = l;
    if (col2 == 0) {
        d_bihp[op] = bih[o];
        d_bhhp[op] = bhh[o];
    }
}

__global__ void k_split_wct() {
    int idx = blockIdx.x * blockDim.x + threadIdx.x;
    if (idx >= G3D * Dd / 2) return;
    float2 v = ((const float2*)d_Wct)[idx];
    __nv_bfloat162 h, l;
    split2(v.x, v.y, h, l);
    ((__nv_bfloat162*)d_Wcthi)[idx] = h;
    ((__nv_bfloat162*)d_Wctlo)[idx] = l;
}

// ---------------- mma.sync helpers --------------------------------------------
__device__ __forceinline__ uint32_t cvta_s(const void* p) {
    return (uint32_t)__cvta_generic_to_shared(p);
}
__device__ __forceinline__ void ldsm_x4(uint32_t& r0, uint32_t& r1, uint32_t& r2, uint32_t& r3,
                                        uint32_t addr) {
    asm volatile("ldmatrix.sync.aligned.m8n8.x4.shared.b16 {%0,%1,%2,%3}, [%4];"
                 : "=r"(r0), "=r"(r1), "=r"(r2), "=r"(r3) : "r"(addr));
}
__device__ __forceinline__ void ldsm_x2(uint32_t& r0, uint32_t& r1, uint32_t addr) {
    asm volatile("ldmatrix.sync.aligned.m8n8.x2.shared.b16 {%0,%1}, [%2];"
                 : "=r"(r0), "=r"(r1) : "r"(addr));
}
__device__ __forceinline__ void mma_bf16(float* d, const uint32_t* a, const uint32_t* b) {
    asm volatile(
        "mma.sync.aligned.m16n8k16.row.col.f32.bf16.bf16.f32 "
        "{%0,%1,%2,%3}, {%4,%5,%6,%7}, {%8,%9}, {%0,%1,%2,%3};"
        : "+f"(d[0]), "+f"(d[1]), "+f"(d[2]), "+f"(d[3])
        : "r"(a[0]), "r"(a[1]), "r"(a[2]), "r"(a[3]), "r"(b[0]), "r"(b[1]));
}
#define CP16(dst, src) \
    asm volatile("cp.async.cg.shared.global [%0], [%1], 16;" :: "r"(dst), "l"(src))
#define CP_COMMIT() asm volatile("cp.async.commit_group;" ::: "memory")

#define SPAD 40

// ---------------- pre-split bf16 GEMM (128x128x32) ----------------------------
#define ARR_BYTES (128 * SPAD * 2)
#define STAGE_BYTES (4 * ARR_BYTES)
#define GEMM_SMEM (2 * STAGE_BYTES)

__global__ __launch_bounds__(256, 2) void gemm_pre(
    const __nv_bfloat16* __restrict__ Ahi, const __nv_bfloat16* __restrict__ Alo,
    const __nv_bfloat16* __restrict__ Bhi, const __nv_bfloat16* __restrict__ Blo,
    float* __restrict__ C, const float* __restrict__ bias,
    int N, int K)
{
    extern __shared__ char smem[];
    const uint32_t sb = cvta_s(smem);
    const int t    = threadIdx.x;
    const int wid  = t >> 5;
    const int lane = t & 31;
    const int wm   = wid >> 2;
    const int wn   = wid & 3;
    const int m0   = blockIdx.y * 128;
    const int n0   = blockIdx.x * 128;
    const int lrow = t >> 2;
    const int lc4  = t & 3;

    float acc[4][4][4];
    #pragma unroll
    for (int mf = 0; mf < 4; mf++)
        #pragma unroll
        for (int nf = 0; nf < 4; nf++)
            #pragma unroll
            for (int j = 0; j < 4; j++) acc[mf][nf][j] = 0.0f;

    const int nchunks = K >> 5;

    auto load_stage = [&](int kc, int s) {
        uint32_t base = sb + s * STAGE_BYTES;
        #pragma unroll
        for (int i = 0; i < 2; i++) {
            int row = lrow + i * 64;
            uint32_t doff = (uint32_t)(row * (SPAD * 2) + lc4 * 16);
            size_t asrc = (size_t)(m0 + row) * K + kc * 32 + lc4 * 8;
            size_t bsrc = (size_t)(n0 + row) * K + kc * 32 + lc4 * 8;
            CP16(base + 0 * ARR_BYTES + doff, Ahi + asrc);
            CP16(base + 1 * ARR_BYTES + doff, Alo + asrc);
            CP16(base + 2 * ARR_BYTES + doff, Bhi + bsrc);
            CP16(base + 3 * ARR_BYTES + doff, Blo + bsrc);
        }
        CP_COMMIT();
    };

    load_stage(0, 0);

    for (int kc = 0; kc < nchunks; kc++) {
        const int s = kc & 1;
        if (kc + 1 < nchunks) {
            load_stage(kc + 1, s ^ 1);
            asm volatile("cp.async.wait_group 1;" ::: "memory");
        } else {
            asm volatile("cp.async.wait_group 0;" ::: "memory");
        }
        __syncthreads();

        const uint32_t base = sb + s * STAGE_BYTES;
        #pragma unroll
        for (int ks = 0; ks < 2; ks++) {
            const int k0 = ks * 16;
            uint32_t ahi[4][4], alo[4][4], bhi[4][2], blo[4][2];
            #pragma unroll
            for (int mf = 0; mf < 4; mf++) {
                int arow = wm * 64 + mf * 16 + (lane & 15);
                int acol = k0 + ((lane >> 4) & 1) * 8;
                uint32_t ao = (uint32_t)((arow * SPAD + acol) * 2);
                ldsm_x4(ahi[mf][0], ahi[mf][1], ahi[mf][2], ahi[mf][3], base + 0 * ARR_BYTES + ao);
                ldsm_x4(alo[mf][0], alo[mf][1], alo[mf][2], alo[mf][3], base + 1 * ARR_BYTES + ao);
            }
            #pragma unroll
            for (int nf = 0; nf < 4; nf++) {
                int brow = wn * 32 + nf * 8 + (lane & 7);
                int bcol = k0 + ((lane >> 3) & 1) * 8;
                uint32_t bo = (uint32_t)((brow * SPAD + bcol) * 2);
                ldsm_x2(bhi[nf][0], bhi[nf][1], base + 2 * ARR_BYTES + bo);
                ldsm_x2(blo[nf][0], blo[nf][1], base + 3 * ARR_BYTES + bo);
            }
            #pragma unroll
            for (int mf = 0; mf < 4; mf++)
                #pragma unroll
                for (int nf = 0; nf < 4; nf++) {
                    mma_bf16(acc[mf][nf], ahi[mf], bhi[nf]);
                    mma_bf16(acc[mf][nf], alo[mf], bhi[nf]);
                    mma_bf16(acc[mf][nf], ahi[mf], blo[nf]);
                }
        }
        __syncthreads();
    }

    const int erow = (lane >> 2);
    const int ecol = (lane & 3) * 2;
    #pragma unroll
    for (int mf = 0; mf < 4; mf++) {
        #pragma unroll
        for (int nf = 0; nf < 4; nf++) {
            int r0 = m0 + wm * 64 + mf * 16 + erow;
            int c0 = n0 + wn * 32 + nf * 8 + ecol;
            float b0 = 0.f, b1 = 0.f;
            if (bias) { b0 = bias[c0]; b1 = bias[c0 + 1]; }
            float2 v0 = make_float2(acc[mf][nf][0] + b0, acc[mf][nf][1] + b1);
            float2 v1 = make_float2(acc[mf][nf][2] + b0, acc[mf][nf][3] + b1);
            *(float2*)(C + (size_t)r0 * N + c0)       = v0;
            *(float2*)(C + (size_t)(r0 + 8) * N + c0) = v1;
        }
    }
}

// ---------------- fused gh GEMM (128x96x32) + GRU epilogue -------------------
// B rows permuted (o' layout); a 96-col tile = 32 features x 3 gates.
#define FA_BYTES (128 * SPAD * 2)   // 10240
#define FB_BYTES (96 * SPAD * 2)    // 7680
#define F_OFF_ALO FA_BYTES
#define F_OFF_BHI (2 * FA_BYTES)
#define F_OFF_BLO (2 * FA_BYTES + FB_BYTES)
#define F_STAGE   (2 * FA_BYTES + 2 * FB_BYTES)   // 35840
#define FUSE_SMEM (2 * F_STAGE)                   // 71680 (>= 128*100*4=51200)

__device__ __forceinline__ float sigmoidf_(float x) {
    return 1.0f / (1.0f + __expf(-x));
}

__global__ __launch_bounds__(256, 2) void gemm_gru(
    const __nv_bfloat16* __restrict__ Ahi, const __nv_bfloat16* __restrict__ Alo,
    const __nv_bfloat16* __restrict__ Bhi, const __nv_bfloat16* __restrict__ Blo,
    const float* __restrict__ gi, const float* __restrict__ bhhp,
    const float* __restrict__ x, const int* __restrict__ mask,
    float* __restrict__ out, int K)
{
    extern __shared__ char smem[];
    const uint32_t sb = cvta_s(smem);
    const int t    = threadIdx.x;
    const int wid  = t >> 5;
    const int lane = t & 31;
    const int wm   = wid >> 2;        // 0..1
    const int wn   = wid & 3;         // 0..3 (24-col slices)
    const int m0   = blockIdx.y * 128;
    const int n0   = blockIdx.x * 96;
    const int lrow = t >> 2;
    const int lc4  = t & 3;

    float acc[4][3][4];
    #pragma unroll
    for (int mf = 0; mf < 4; mf++)
        #pragma unroll
        for (int nf = 0; nf < 3; nf++)
            #pragma unroll
            for (int j = 0; j < 4; j++) acc[mf][nf][j] = 0.0f;

    const int nchunks = K >> 5;

    auto load_stage = [&](int kc, int s) {
        uint32_t base = sb + s * F_STAGE;
        #pragma unroll
        for (int i = 0; i < 2; i++) {
            int row = lrow + i * 64;
            uint32_t doff = (uint32_t)(row * (SPAD * 2) + lc4 * 16);
            size_t asrc = (size_t)(m0 + row) * K + kc * 32 + lc4 * 8;
            CP16(base + 0 + doff, Ahi + asrc);
            CP16(base + F_OFF_ALO + doff, Alo + asrc);
        }
        {   // B: 96 rows * 4 chunks = 384; thread t does c=t, and c=t+256 if t<128
            int c = t;
            int row = c >> 2, c4 = c & 3;
            uint32_t doff = (uint32_t)(row * (SPAD * 2) + c4 * 16);
            size_t bsrc = (size_t)(n0 + row) * K + kc * 32 + c4 * 8;
            CP16(base + F_OFF_BHI + doff, Bhi + bsrc);
            CP16(base + F_OFF_BLO + doff, Blo + bsrc);
            if (t < 128) {
                c = t + 256;
                row = c >> 2; c4 = c & 3;
                doff = (uint32_t)(row * (SPAD * 2) + c4 * 16);
                bsrc = (size_t)(n0 + row) * K + kc * 32 + c4 * 8;
                CP16(base + F_OFF_BHI + doff, Bhi + bsrc);
                CP16(base + F_OFF_BLO + doff, Blo + bsrc);
            }
        }
        CP_COMMIT();
    };

    load_stage(0, 0);

    for (int kc = 0; kc < nchunks; kc++) {
        const int s = kc & 1;
        if (kc + 1 < nchunks) {
            load_stage(kc + 1, s ^ 1);
            asm volatile("cp.async.wait_group 1;" ::: "memory");
        } else {
            asm volatile("cp.async.wait_group 0;" ::: "memory");
        }
        __syncthreads();

        const uint32_t base = sb + s * F_STAGE;
        #pragma unroll
        for (int ks = 0; ks < 2; ks++) {
            const int k0 = ks * 16;
            uint32_t ahi[4][4], alo[4][4], bhi[3][2], blo[3][2];
            #pragma unroll
            for (int mf = 0; mf < 4; mf++) {
                int arow = wm * 64 + mf * 16 + (lane & 15);
                int acol = k0 + ((lane >> 4) & 1) * 8;
                uint32_t ao = (uint32_t)((arow * SPAD + acol) * 2);
                ldsm_x4(ahi[mf][0], ahi[mf][1], ahi[mf][2], ahi[mf][3], base + 0 + ao);
                ldsm_x4(alo[mf][0], alo[mf][1], alo[mf][2], alo[mf][3], base + F_OFF_ALO + ao);
            }
            #pragma unroll
            for (int nf = 0; nf < 3; nf++) {
                int brow = wn * 24 + nf * 8 + (lane & 7);
                int bcol = k0 + ((lane >> 3) & 1) * 8;
                uint32_t bo = (uint32_t)((brow * SPAD + bcol) * 2);
                ldsm_x2(bhi[nf][0], bhi[nf][1], base + F_OFF_BHI + bo);
                ldsm_x2(blo[nf][0], blo[nf][1], base + F_OFF_BLO + bo);
            }
            #pragma unroll
            for (int mf = 0; mf < 4; mf++)
                #pragma unroll
                for (int nf = 0; nf < 3; nf++) {
                    mma_bf16(acc[mf][nf], ahi[mf], bhi[nf]);
                    mma_bf16(acc[mf][nf], alo[mf], bhi[nf]);
                    mma_bf16(acc[mf][nf], ahi[mf], blo[nf]);
                }
        }
        __syncthreads();
    }

    // phase 1: fragments -> smem tile ghs[128][100]
    float* ghs = (float*)smem;
    const int erow = (lane >> 2);
    const int ecol = (lane & 3) * 2;
    #pragma unroll
    for (int mf = 0; mf < 4; mf++) {
        #pragma unroll
        for (int nf = 0; nf < 3; nf++) {
            int r0 = wm * 64 + mf * 16 + erow;
            int c0 = wn * 24 + nf * 8 + ecol;
            *(float2*)&ghs[r0 * 100 + c0]       = make_float2(acc[mf][nf][0], acc[mf][nf][1]);
            *(float2*)&ghs[(r0 + 8) * 100 + c0] = make_float2(acc[mf][nf][2], acc[mf][nf][3]);
        }
    }
    __syncthreads();

    // phase 2: GRU. thread t: feature f = t&31; rows r = (t>>5)*16 + 0..15
    const int f    = t & 31;
    const int rg0  = (t >> 5) * 16;
    const int fglob = blockIdx.x * 32 + f;
    const float bh_r = bhhp[n0 + f];
    const float bh_z = bhhp[n0 + 32 + f];
    const float bh_n = bhhp[n0 + 64 + f];

    #pragma unroll
    for (int i = 0; i < 16; i++) {
        int r = rg0 + i;
        int row_g = m0 + r;
        float valid = (mask[row_g] > 0) ? 1.0f : 0.0f;
        const float* gip = gi + (size_t)row_g * G3D + n0;
        float gi_r = gip[f];
        float gi_z = gip[32 + f];
        float gi_n = gip[64 + f];
        float gh_r = ghs[r * 100 + f]      + bh_r;
        float gh_z = ghs[r * 100 + 32 + f] + bh_z;
        float gh_n = ghs[r * 100 + 64 + f] + bh_n;
        float xv = x[(size_t)row_g * Dd + fglob];
        float rr = sigmoidf_(gi_r + gh_r);
        float zz = sigmoidf_(gi_z + gh_z);
        float nn = tanhf(gi_n + rr * gh_n);
        out[(size_t)row_g * Dd + fglob] = ((1.0f - zz) * nn + zz * xv) * valid;
    }
}

// ---------------- aggregation on x (writes split bf16) -----------------------
__global__ void k_aggregate(const float* __restrict__ x) {
    int node = blockIdx.x;
    int t = threadIdx.x;
    int start = d_rowptr[node];
    int end   = d_rowptr[node + 1];
    int bBase = (node >> 12) << 12;
    float4 acc = make_float4(0.f, 0.f, 0.f, 0.f);
    for (int j = start; j < end; j++) {
        int src = d_esrc[j];
        float w = d_eww[j];
        float4 xv = __ldg((const float4*)&x[(size_t)(bBase + src) * Dd] + t);
        acc.x += w * xv.x; acc.y += w * xv.y; acc.z += w * xv.z; acc.w += w * xv.w;
    }
    __nv_bfloat162 h0, l0, h1, l1;
    split2(acc.x, acc.y, h0, l0);
    split2(acc.z, acc.w, h1, l1);
    size_t o = (size_t)node * (Dd / 2) + t * 2;
    ((__nv_bfloat162*)d_agghi)[o]     = h0;
    ((__nv_bfloat162*)d_agghi)[o + 1] = h1;
    ((__nv_bfloat162*)d_agglo)[o]     = l0;
    ((__nv_bfloat162*)d_agglo)[o + 1] = l1;
}

// ---------------- launch ------------------------------------------------------
extern "C" void kernel_launch(void* const* d_in, const int* in_sizes, int n_in,
                              void* d_out, int out_size) {
    const float* x    = (const float*)d_in[0];
    const int*   ei   = (const int*)  d_in[1];
    const float* ew   = (const float*)d_in[2];
    const int*   mask = (const int*)  d_in[3];
    const float* W    = (const float*)d_in[4];
    const float* Wih  = (const float*)d_in[5];
    const float* Whh  = (const float*)d_in[6];
    const float* bih  = (const float*)d_in[7];
    const float* bhh  = (const float*)d_in[8];
    float* out = (float*)d_out;

    float *p_gi, *p_wct, *p_bihp, *p_bhhp;
    __nv_bfloat16 *p_xhi, *p_xlo, *p_agghi, *p_agglo;
    __nv_bfloat16 *p_whi, *p_wlo, *p_wihphi, *p_wihplo, *p_whhphi, *p_whhplo, *p_wcthi, *p_wctlo;
    cudaGetSymbolAddress((void**)&p_gi,     d_gi);
    cudaGetSymbolAddress((void**)&p_wct,    d_Wct);
    cudaGetSymbolAddress((void**)&p_bihp,   d_bihp);
    cudaGetSymbolAddress((void**)&p_bhhp,   d_bhhp);
    cudaGetSymbolAddress((void**)&p_xhi,    d_xhi);
    cudaGetSymbolAddress((void**)&p_xlo,    d_xlo);
    cudaGetSymbolAddress((void**)&p_agghi,  d_agghi);
    cudaGetSymbolAddress((void**)&p_agglo,  d_agglo);
    cudaGetSymbolAddress((void**)&p_whi,    d_Whi);
    cudaGetSymbolAddress((void**)&p_wlo,    d_Wlo);
    cudaGetSymbolAddress((void**)&p_wihphi, d_Wihphi);
    cudaGetSymbolAddress((void**)&p_wihplo, d_Wihplo);
    cudaGetSymbolAddress((void**)&p_whhphi, d_Whhphi);
    cudaGetSymbolAddress((void**)&p_whhplo, d_Whhplo);
    cudaGetSymbolAddress((void**)&p_wcthi,  d_Wcthi);
    cudaGetSymbolAddress((void**)&p_wctlo,  d_Wctlo);

    cudaFuncSetAttribute(gemm_pre, cudaFuncAttributeMaxDynamicSharedMemorySize, GEMM_SMEM);
    cudaFuncSetAttribute(gemm_gru, cudaFuncAttributeMaxDynamicSharedMemorySize, FUSE_SMEM);

    // CSR build
    k_zero<<<(NODES + 255) / 256, 256>>>();
    k_count<<<EDGES / 256, 256>>>(ei, mask);
    k_scan<<<1, 1024>>>();
    k_fill<<<EDGES / 256, 256>>>(ei, mask, ew);

    // splits + permutes
    k_split_x<<<(NODES * Dd / 2 + 255) / 256, 256>>>(x);
    k_split_W<<<(Dd * Dd / 2 + 255) / 256, 256>>>(W);
    k_permsplit<<<(G3D * Dd / 2 + 255) / 256, 256>>>(Wih, Whh, bih, bhh);

    // Wct = Wih(perm) @ W^T : [768,256], rows already permuted
    {
        dim3 grid(Dd / 128, G3D / 128);     // (2, 6)
        gemm_pre<<<grid, 256, GEMM_SMEM>>>(p_wihphi, p_wihplo, p_whi, p_wlo, p_wct, nullptr, Dd, Dd);
    }
    k_split_wct<<<(G3D * Dd / 2 + 255) / 256, 256>>>();

    // aggx = segment_sum(x[u] * w, v), split bf16
    k_aggregate<<<NODES, 64>>>(x);

    // gi = aggx @ Wct^T + bihp   (permuted-col layout)
    {
        dim3 grid(G3D / 128, NODES / 128);  // (6, 256)
        gemm_pre<<<grid, 256, GEMM_SMEM>>>(p_agghi, p_agglo, p_wcthi, p_wctlo, p_gi, p_bihp, G3D, Dd);
    }

    // gh = x @ Whh(perm)^T fused with GRU -> out
    {
        dim3 grid(G3D / 96, NODES / 128);   // (8, 256)
        gemm_gru<<<grid, 256, FUSE_SMEM>>>(p_xhi, p_xlo, p_whhphi, p_whhplo,
                                           p_gi, p_bhhp, x, mask, out, Dd);
    }
}